// round 11
// baseline (speedup 1.0000x reference)
#include <cuda_runtime.h>
#include <cstdint>

#define VOCAB 67
#define EMB 50
#define NLAYERS 8
#define REP_FLOATS 4824       // 67 rows * 72 floats
#define TAB_FLOATS (4*REP_FLOATS)
#define GRID 2048

// Precomputed per-token logits, 4 shifted replicas (pads 0,3,2,1), rows 72 floats.
__device__ __align__(16) float g_tab[TAB_FLOATS];
__device__ int g_count;   // table-rows-done counter (self-resetting)
__device__ int g_exit;    // block-exit counter    (self-resetting)

// ---------------------------------------------------------------------------
// cp.async helpers
// ---------------------------------------------------------------------------
__device__ __forceinline__ void cp16(uint32_t s, const void* g) {
    asm volatile("cp.async.cg.shared.global [%0], [%1], 16;" :: "r"(s), "l"(g));
}
__device__ __forceinline__ void cp_commit() { asm volatile("cp.async.commit_group;"); }
template<int N> __device__ __forceinline__ void cp_wait() {
    asm volatile("cp.async.wait_group %0;" :: "n"(N));
}

__device__ __forceinline__ void stcs128(float4* p, float4 v) {
    asm volatile("st.global.cs.v4.f32 [%0], {%1,%2,%3,%4};"
                 :: "l"(p), "f"(v.x), "f"(v.y), "f"(v.z), "f"(v.w) : "memory");
}

// ---------------------------------------------------------------------------
// Fused kernel. Blocks 0..66 compute their token's logits row (verified R7
// double-buffered table code, 256-thread staging), release via g_count.
// All 2048 blocks then run the verified R7 gather body: one warp = 32
// consecutive tokens = 536 float4s, coalesced .cs STG.128, one shfl/step,
// one aligned LDG.128 per quad + predicated straddle fixup.
// Counters self-reset by the last exiting block (clean state every replay).
// ---------------------------------------------------------------------------
__global__ void __launch_bounds__(256, 5) fused_kernel(
    const int*   __restrict__ idx,    // [64*8192]
    const float* __restrict__ emb,    // [67,50]
    const float* __restrict__ kappa,  // [8,50,50]
    const float* __restrict__ phi,    // [8,50,50]
    const float* __restrict__ W_out,  // [50,67]
    const float* __restrict__ b_out,  // [67]
    float*       __restrict__ out)
{
    __shared__ __align__(16) float w[2][2*EMB*EMB];   // 40000 B: {K,P} x 2 buffers
    __shared__ float sar[2][EMB], sai[2][EMB], sint[EMB];

    const int tid = threadIdx.x;
    const int b   = blockIdx.x;

    // ---------------- phase 1: table (blocks 0..66 only) ----------------
    if (b < VOCAB) {
        const int t = b;
        const uint32_t s0 = (uint32_t)__cvta_generic_to_shared(&w[0][0]);
        const uint32_t s1 = (uint32_t)__cvta_generic_to_shared(&w[1][0]);

        if (tid < EMB) { sar[0][tid] = emb[t*EMB + tid]; sai[0][tid] = 0.f; }

        // prefetch layer 0 into buffer 0 (625 float4 per matrix, 256 threads)
        #pragma unroll
        for (int i = 0; i < 3; ++i) {
            int j = tid + i*256;
            if (j < 625) {
                cp16(s0 + j*16,         kappa + j*4);
                cp16(s0 + 10000 + j*16, phi   + j*4);
            }
        }
        cp_commit();

        for (int l = 0; l < NLAYERS; ++l) {
            const int buf = l & 1;
            if (l + 1 < NLAYERS) {
                const uint32_t d = buf ? s0 : s1;
                const float* gK = kappa + (l+1)*EMB*EMB;
                const float* gP = phi   + (l+1)*EMB*EMB;
                #pragma unroll
                for (int i = 0; i < 3; ++i) {
                    int j = tid + i*256;
                    if (j < 625) {
                        cp16(d + j*16,         gK + j*4);
                        cp16(d + 10000 + j*16, gP + j*4);
                    }
                }
                cp_commit();
                cp_wait<1>();
            } else {
                cp_wait<0>();
            }
            __syncthreads();

            const int cur = l & 1, nxt = cur ^ 1;
            const float* K = &w[buf][0];
            const float* P = K + 2500;
            if (tid < EMB) {                           // real, f = tid
                float a0=0.f,a1=0.f,a2=0.f,a3=0.f;
                #pragma unroll
                for (int e = 0; e < 48; e += 4) {
                    a0 += sar[cur][e+0]*K[(e+0)*EMB+tid] - sai[cur][e+0]*P[(e+0)*EMB+tid];
                    a1 += sar[cur][e+1]*K[(e+1)*EMB+tid] - sai[cur][e+1]*P[(e+1)*EMB+tid];
                    a2 += sar[cur][e+2]*K[(e+2)*EMB+tid] - sai[cur][e+2]*P[(e+2)*EMB+tid];
                    a3 += sar[cur][e+3]*K[(e+3)*EMB+tid] - sai[cur][e+3]*P[(e+3)*EMB+tid];
                }
                a0 += sar[cur][48]*K[48*EMB+tid] - sai[cur][48]*P[48*EMB+tid];
                a1 += sar[cur][49]*K[49*EMB+tid] - sai[cur][49]*P[49*EMB+tid];
                sar[nxt][tid] = (a0+a1) + (a2+a3);
            } else if (tid >= 64 && tid < 64 + EMB) {  // imag, f = tid-64
                const int f = tid - 64;
                float a0=0.f,a1=0.f,a2=0.f,a3=0.f;
                #pragma unroll
                for (int e = 0; e < 48; e += 4) {
                    a0 += sar[cur][e+0]*P[(e+0)*EMB+f] + sai[cur][e+0]*K[(e+0)*EMB+f];
                    a1 += sar[cur][e+1]*P[(e+1)*EMB+f] + sai[cur][e+1]*K[(e+1)*EMB+f];
                    a2 += sar[cur][e+2]*P[(e+2)*EMB+f] + sai[cur][e+2]*K[(e+2)*EMB+f];
                    a3 += sar[cur][e+3]*P[(e+3)*EMB+f] + sai[cur][e+3]*K[(e+3)*EMB+f];
                }
                a0 += sar[cur][48]*P[48*EMB+f] + sai[cur][48]*K[48*EMB+f];
                a1 += sar[cur][49]*P[49*EMB+f] + sai[cur][49]*K[49*EMB+f];
                sai[nxt][f] = (a0+a1) + (a2+a3);
            }
            __syncthreads();
        }

        if (tid < EMB) {
            float a = sar[0][tid], c = sai[0][tid];
            sint[tid] = a*a + c*c;
        }
        __syncthreads();
        if (tid < VOCAB) {
            float acc = __ldg(b_out + tid);
            #pragma unroll
            for (int e = 0; e < EMB; ++e)
                acc += sint[e] * __ldg(W_out + e*VOCAB + tid);
            g_tab[0*REP_FLOATS + t*72 + tid + 0] = acc;
            g_tab[1*REP_FLOATS + t*72 + tid + 3] = acc;
            g_tab[2*REP_FLOATS + t*72 + tid + 2] = acc;
            g_tab[3*REP_FLOATS + t*72 + tid + 1] = acc;
        }
        __syncthreads();                 // all row writes issued
        __threadfence();                 // release (cumulative after bar)
        if (tid == 0) atomicAdd(&g_count, 1);
    }

    // ---------------- barrier: wait for all 67 table rows ----------------
    if (tid == 0) {
        while (*(volatile int*)&g_count < VOCAB) __nanosleep(128);
    }
    __syncthreads();
    __threadfence();                     // acquire

    // ---------------- phase 2: gather (verified R7 body) ----------------
    {
        const int lane = tid & 31;
        const int warp = b * 8 + (tid >> 5);             // 0..16383

        const int mytok = __ldg(idx + warp*32 + lane);   // token ids < 67
        const int nx    = __shfl_down_sync(0xffffffffu, mytok, 1);
        const int pair  = mytok | (nx << 8);
        float4* O = (float4*)out + (uint32_t)warp * 536;

        #pragma unroll
        for (int i = 0; i < 17; ++i) {
            const int p4 = lane + 32*i;
            const int e0 = 4*p4;
            const int tk = (int)((unsigned)e0 / 67u);    // owning token slot
            const int r  = e0 - 67*tk;

            const int pp     = __shfl_sync(0xffffffffu, pair, tk & 31);
            const int token  = pp & 0xff;
            const int token2 = (pp >> 8) & 0xff;

            const int j   = tk & 3;                      // == r & 3
            const int pos = (r + 3) & ~3;                // 16B-aligned
            float4 v = __ldg((const float4*)(g_tab + j*REP_FLOATS + token*72 + pos));

            if (r >= 64) {                               // straddle fixup
                float4 x = __ldg((const float4*)(g_tab + (j+1)*REP_FLOATS + token2*72));
                if (r == 66) v.y = x.y;
                if (r >= 65) v.z = x.z;
                v.w = x.w;
            }
            if (i < 16 || lane < 24)
                stcs128(O + p4, v);
        }
    }

    // ---------------- exit: last block resets counters ----------------
    __syncthreads();
    if (tid == 0) {
        int old = atomicAdd(&g_exit, 1);
        if (old == (int)gridDim.x - 1) {   // last block: clean state for next run
            g_count = 0;
            g_exit  = 0;
        }
    }
}

// ---------------------------------------------------------------------------
// Launch: single fused kernel (saves one launch + inter-kernel gap).
// ---------------------------------------------------------------------------
extern "C" void kernel_launch(void* const* d_in, const int* in_sizes, int n_in,
                              void* d_out, int out_size) {
    const int*   idx = (const int*)d_in[0];   // input_seq [64,8192] int32
    const float* emb = (const float*)d_in[1]; // embedding_table [67,50]
    const float* kap = (const float*)d_in[2]; // kappa [8,50,50]
    const float* ph  = (const float*)d_in[3]; // phi   [8,50,50]
    const float* Wo  = (const float*)d_in[4]; // W_out [50,67]
    const float* bo  = (const float*)d_in[5]; // b_out [67]
    float* out = (float*)d_out;

    fused_kernel<<<GRID, 256>>>(idx, emb, kap, ph, Wo, bo, out);
}

// round 12
// speedup vs baseline: 1.2244x; 1.2244x over previous
#include <cuda_runtime.h>
#include <cstdint>

#define VOCAB 67
#define EMB 50
#define NLAYERS 8
#define NTILES 16384          // (64*8192)/32 tokens per tile
#define REP_FLOATS 4824       // 67 rows * 72 floats
#define TAB_FLOATS (4*REP_FLOATS)
#define GBLOCKS 1184          // 148 SMs x 8 blocks of 256 = 9472 warps = ONE wave

// Precomputed per-token logits, stored as 4 shifted replicas:
// replica j stores row element e at padded position e + pad_j (pads 0,3,2,1), rows 72 floats.
__device__ __align__(16) float g_tab[TAB_FLOATS];

// ---------------------------------------------------------------------------
// cp.async helpers
// ---------------------------------------------------------------------------
__device__ __forceinline__ void cp16(uint32_t s, const void* g) {
    asm volatile("cp.async.cg.shared.global [%0], [%1], 16;" :: "r"(s), "l"(g));
}
__device__ __forceinline__ void cp_commit() { asm volatile("cp.async.commit_group;"); }
template<int N> __device__ __forceinline__ void cp_wait() {
    asm volatile("cp.async.wait_group %0;" :: "n"(N));
}

// ---------------------------------------------------------------------------
// Kernel 1: per-token logits table — verified R7 version (40KB static smem,
// double-buffered cp.async, 4-way split accumulators).
// ---------------------------------------------------------------------------
__global__ void __launch_bounds__(128) table_kernel(
    const float* __restrict__ emb,   // [67,50]
    const float* __restrict__ kappa, // [8,50,50]
    const float* __restrict__ phi,   // [8,50,50]
    const float* __restrict__ W_out, // [50,67]
    const float* __restrict__ b_out) // [67]
{
    const int t   = blockIdx.x;
    const int tid = threadIdx.x;

    __shared__ __align__(16) float wK[2][EMB*EMB], wP[2][EMB*EMB];  // 40 KB
    __shared__ float sar[2][EMB], sai[2][EMB], sint[EMB];

    const uint32_t sK0 = (uint32_t)__cvta_generic_to_shared(&wK[0][0]);
    const uint32_t sK1 = (uint32_t)__cvta_generic_to_shared(&wK[1][0]);
    const uint32_t sP0 = (uint32_t)__cvta_generic_to_shared(&wP[0][0]);
    const uint32_t sP1 = (uint32_t)__cvta_generic_to_shared(&wP[1][0]);

    if (tid < EMB) { sar[0][tid] = emb[t*EMB + tid]; sai[0][tid] = 0.f; }

    #pragma unroll
    for (int i = 0; i < 5; ++i) {
        int j = tid + i*128;
        if (j < 625) {
            cp16(sK0 + j*16, kappa + j*4);
            cp16(sP0 + j*16, phi   + j*4);
        }
    }
    cp_commit();

    for (int l = 0; l < NLAYERS; ++l) {
        const int buf = l & 1;
        if (l + 1 < NLAYERS) {
            const uint32_t dK = (buf ? sK0 : sK1), dP = (buf ? sP0 : sP1);
            const float* gK = kappa + (l+1)*EMB*EMB;
            const float* gP = phi   + (l+1)*EMB*EMB;
            #pragma unroll
            for (int i = 0; i < 5; ++i) {
                int j = tid + i*128;
                if (j < 625) {
                    cp16(dK + j*16, gK + j*4);
                    cp16(dP + j*16, gP + j*4);
                }
            }
            cp_commit();
            cp_wait<1>();
        } else {
            cp_wait<0>();
        }
        __syncthreads();

        const int cur = l & 1, nxt = cur ^ 1;
        const float* K = wK[buf];
        const float* P = wP[buf];
        if (tid < EMB) {                       // real, f = tid
            float a0=0.f,a1=0.f,a2=0.f,a3=0.f;
            #pragma unroll
            for (int e = 0; e < 48; e += 4) {
                a0 += sar[cur][e+0]*K[(e+0)*EMB+tid] - sai[cur][e+0]*P[(e+0)*EMB+tid];
                a1 += sar[cur][e+1]*K[(e+1)*EMB+tid] - sai[cur][e+1]*P[(e+1)*EMB+tid];
                a2 += sar[cur][e+2]*K[(e+2)*EMB+tid] - sai[cur][e+2]*P[(e+2)*EMB+tid];
                a3 += sar[cur][e+3]*K[(e+3)*EMB+tid] - sai[cur][e+3]*P[(e+3)*EMB+tid];
            }
            a0 += sar[cur][48]*K[48*EMB+tid] - sai[cur][48]*P[48*EMB+tid];
            a1 += sar[cur][49]*K[49*EMB+tid] - sai[cur][49]*P[49*EMB+tid];
            sar[nxt][tid] = (a0+a1) + (a2+a3);
        } else if (tid >= 64 && tid < 64 + EMB) {  // imag, f = tid-64
            const int f = tid - 64;
            float a0=0.f,a1=0.f,a2=0.f,a3=0.f;
            #pragma unroll
            for (int e = 0; e < 48; e += 4) {
                a0 += sar[cur][e+0]*P[(e+0)*EMB+f] + sai[cur][e+0]*K[(e+0)*EMB+f];
                a1 += sar[cur][e+1]*P[(e+1)*EMB+f] + sai[cur][e+1]*K[(e+1)*EMB+f];
                a2 += sar[cur][e+2]*P[(e+2)*EMB+f] + sai[cur][e+2]*K[(e+2)*EMB+f];
                a3 += sar[cur][e+3]*P[(e+3)*EMB+f] + sai[cur][e+3]*K[(e+3)*EMB+f];
            }
            a0 += sar[cur][48]*P[48*EMB+f] + sai[cur][48]*K[48*EMB+f];
            a1 += sar[cur][49]*P[49*EMB+f] + sai[cur][49]*K[49*EMB+f];
            sai[nxt][f] = (a0+a1) + (a2+a3);
        }
        __syncthreads();
    }

    if (tid < EMB) {
        float a = sar[0][tid], b = sai[0][tid];
        sint[tid] = a*a + b*b;
    }
    __syncthreads();
    if (tid < VOCAB) {
        float acc = __ldg(b_out + tid);
        #pragma unroll
        for (int e = 0; e < EMB; ++e)
            acc += sint[e] * __ldg(W_out + e*VOCAB + tid);
        g_tab[0*REP_FLOATS + t*72 + tid + 0] = acc;
        g_tab[1*REP_FLOATS + t*72 + tid + 3] = acc;
        g_tab[2*REP_FLOATS + t*72 + tid + 2] = acc;
        g_tab[3*REP_FLOATS + t*72 + tid + 1] = acc;
    }
}

// ---------------------------------------------------------------------------
// Kernel 2: gather — R7 body (verified 24.2us @ 38 regs) wrapped in a
// GRID-STRIDE loop so the body exists ONCE in SASS (regs stay low; R9's
// unrolled duplication hit 163 regs). Grid = exactly one resident wave
// (1184 blocks x 256 = 9472 warps); warps take tiles warp, warp+9472 ->
// no underpopulated second wave (R7 ran 1.73 waves at 60% achieved occ).
// ---------------------------------------------------------------------------
__device__ __forceinline__ void stcs128(float4* p, float4 v) {
    asm volatile("st.global.cs.v4.f32 [%0], {%1,%2,%3,%4};"
                 :: "l"(p), "f"(v.x), "f"(v.y), "f"(v.z), "f"(v.w) : "memory");
}

__global__ void __launch_bounds__(256) gather_kernel(
    const int* __restrict__ idx, float* __restrict__ out)
{
    const int lane  = threadIdx.x & 31;
    const int warp0 = (blockIdx.x * 256 + (int)threadIdx.x) >> 5;  // 0..9471
    const int nwarp = (GBLOCKS * 256) >> 5;                        // 9472

    #pragma unroll 1
    for (int tile = warp0; tile < NTILES; tile += nwarp) {
        const int mytok = __ldg(idx + tile*32 + lane);   // token ids < 67 (8 bits)
        const int nxt   = __shfl_down_sync(0xffffffffu, mytok, 1);
        const int pair  = mytok | (nxt << 8);            // {tok[lane], tok[lane+1]}
        float4* O = (float4*)out + (uint32_t)tile * 536;

        #pragma unroll
        for (int i = 0; i < 17; ++i) {
            const int p4 = lane + 32*i;          // output float4 index
            const int e0 = 4*p4;
            const int tk = (int)((unsigned)e0 / 67u);  // owning token slot
            const int r  = e0 - 67*tk;           // element offset within token row

            const int pp     = __shfl_sync(0xffffffffu, pair, tk & 31);
            const int token  = pp & 0xff;
            const int token2 = (pp >> 8) & 0xff;

            const int j   = tk & 3;              // == r & 3 (e0 % 4 == 0)
            const int pos = (r + 3) & ~3;        // r + pad_j, 16B-aligned
            float4 v = __ldg((const float4*)(g_tab + j*REP_FLOATS + token*72 + pos));

            if (r >= 64) {                       // straddle: tail from next token
                float4 w = __ldg((const float4*)(g_tab + (j+1)*REP_FLOATS + token2*72));
                if (r == 66) v.y = w.y;
                if (r >= 65) v.z = w.z;
                v.w = w.w;
            }
            if (i < 16 || lane < 24)             // quads >=536 don't exist
                stcs128(O + p4, v);
        }
    }
}

// ---------------------------------------------------------------------------
// Launch
// ---------------------------------------------------------------------------
extern "C" void kernel_launch(void* const* d_in, const int* in_sizes, int n_in,
                              void* d_out, int out_size) {
    const int*   idx = (const int*)d_in[0];   // input_seq [64,8192] int32
    const float* emb = (const float*)d_in[1]; // embedding_table [67,50]
    const float* kap = (const float*)d_in[2]; // kappa [8,50,50]
    const float* ph  = (const float*)d_in[3]; // phi   [8,50,50]
    const float* Wo  = (const float*)d_in[4]; // W_out [50,67]
    const float* bo  = (const float*)d_in[5]; // b_out [67]
    float* out = (float*)d_out;

    table_kernel<<<VOCAB, 128>>>(emb, kap, ph, Wo, bo);
    gather_kernel<<<GBLOCKS, 256>>>(idx, out);   // single resident wave
}

// round 13
// speedup vs baseline: 1.2767x; 1.0427x over previous
#include <cuda_runtime.h>
#include <cstdint>

#define VOCAB 67
#define EMB 50
#define NLAYERS 8
#define REP_FLOATS 4824       // 67 rows * 72 floats
#define TAB_FLOATS (4*REP_FLOATS)
#define PD 4                  // gather software-pipeline depth

// Precomputed per-token logits, stored as 4 shifted replicas:
// replica j stores row element e at padded position e + pad_j (pads 0,3,2,1), rows 72 floats.
__device__ __align__(16) float g_tab[TAB_FLOATS];

// ---------------------------------------------------------------------------
// cp.async helpers
// ---------------------------------------------------------------------------
__device__ __forceinline__ void cp16(uint32_t s, const void* g) {
    asm volatile("cp.async.cg.shared.global [%0], [%1], 16;" :: "r"(s), "l"(g));
}
__device__ __forceinline__ void cp_commit() { asm volatile("cp.async.commit_group;"); }
template<int N> __device__ __forceinline__ void cp_wait() {
    asm volatile("cp.async.wait_group %0;" :: "n"(N));
}

// ---------------------------------------------------------------------------
// Kernel 1: per-token logits table — EXACT verified R7 version.
// ---------------------------------------------------------------------------
__global__ void __launch_bounds__(128) table_kernel(
    const float* __restrict__ emb,   // [67,50]
    const float* __restrict__ kappa, // [8,50,50]
    const float* __restrict__ phi,   // [8,50,50]
    const float* __restrict__ W_out, // [50,67]
    const float* __restrict__ b_out) // [67]
{
    const int t   = blockIdx.x;
    const int tid = threadIdx.x;

    __shared__ __align__(16) float wK[2][EMB*EMB], wP[2][EMB*EMB];  // 40 KB
    __shared__ float sar[2][EMB], sai[2][EMB], sint[EMB];

    const uint32_t sK0 = (uint32_t)__cvta_generic_to_shared(&wK[0][0]);
    const uint32_t sK1 = (uint32_t)__cvta_generic_to_shared(&wK[1][0]);
    const uint32_t sP0 = (uint32_t)__cvta_generic_to_shared(&wP[0][0]);
    const uint32_t sP1 = (uint32_t)__cvta_generic_to_shared(&wP[1][0]);

    if (tid < EMB) { sar[0][tid] = emb[t*EMB + tid]; sai[0][tid] = 0.f; }

    #pragma unroll
    for (int i = 0; i < 5; ++i) {
        int j = tid + i*128;
        if (j < 625) {
            cp16(sK0 + j*16, kappa + j*4);
            cp16(sP0 + j*16, phi   + j*4);
        }
    }
    cp_commit();

    for (int l = 0; l < NLAYERS; ++l) {
        const int buf = l & 1;
        if (l + 1 < NLAYERS) {
            const uint32_t dK = (buf ? sK0 : sK1), dP = (buf ? sP0 : sP1);
            const float* gK = kappa + (l+1)*EMB*EMB;
            const float* gP = phi   + (l+1)*EMB*EMB;
            #pragma unroll
            for (int i = 0; i < 5; ++i) {
                int j = tid + i*128;
                if (j < 625) {
                    cp16(dK + j*16, gK + j*4);
                    cp16(dP + j*16, gP + j*4);
                }
            }
            cp_commit();
            cp_wait<1>();
        } else {
            cp_wait<0>();
        }
        __syncthreads();

        const int cur = l & 1, nxt = cur ^ 1;
        const float* K = wK[buf];
        const float* P = wP[buf];
        if (tid < EMB) {                       // real, f = tid
            float a0=0.f,a1=0.f,a2=0.f,a3=0.f;
            #pragma unroll
            for (int e = 0; e < 48; e += 4) {
                a0 += sar[cur][e+0]*K[(e+0)*EMB+tid] - sai[cur][e+0]*P[(e+0)*EMB+tid];
                a1 += sar[cur][e+1]*K[(e+1)*EMB+tid] - sai[cur][e+1]*P[(e+1)*EMB+tid];
                a2 += sar[cur][e+2]*K[(e+2)*EMB+tid] - sai[cur][e+2]*P[(e+2)*EMB+tid];
                a3 += sar[cur][e+3]*K[(e+3)*EMB+tid] - sai[cur][e+3]*P[(e+3)*EMB+tid];
            }
            a0 += sar[cur][48]*K[48*EMB+tid] - sai[cur][48]*P[48*EMB+tid];
            a1 += sar[cur][49]*K[49*EMB+tid] - sai[cur][49]*P[49*EMB+tid];
            sar[nxt][tid] = (a0+a1) + (a2+a3);
        } else if (tid >= 64 && tid < 64 + EMB) {  // imag, f = tid-64
            const int f = tid - 64;
            float a0=0.f,a1=0.f,a2=0.f,a3=0.f;
            #pragma unroll
            for (int e = 0; e < 48; e += 4) {
                a0 += sar[cur][e+0]*P[(e+0)*EMB+f] + sai[cur][e+0]*K[(e+0)*EMB+f];
                a1 += sar[cur][e+1]*P[(e+1)*EMB+f] + sai[cur][e+1]*K[(e+1)*EMB+f];
                a2 += sar[cur][e+2]*P[(e+2)*EMB+f] + sai[cur][e+2]*K[(e+2)*EMB+f];
                a3 += sar[cur][e+3]*P[(e+3)*EMB+f] + sai[cur][e+3]*K[(e+3)*EMB+f];
            }
            a0 += sar[cur][48]*P[48*EMB+f] + sai[cur][48]*K[48*EMB+f];
            a1 += sar[cur][49]*P[49*EMB+f] + sai[cur][49]*K[49*EMB+f];
            sai[nxt][f] = (a0+a1) + (a2+a3);
        }
        __syncthreads();
    }

    if (tid < EMB) {
        float a = sar[0][tid], b = sai[0][tid];
        sint[tid] = a*a + b*b;
    }
    __syncthreads();
    if (tid < VOCAB) {
        float acc = __ldg(b_out + tid);
        #pragma unroll
        for (int e = 0; e < EMB; ++e)
            acc += sint[e] * __ldg(W_out + e*VOCAB + tid);
        g_tab[0*REP_FLOATS + t*72 + tid + 0] = acc;
        g_tab[1*REP_FLOATS + t*72 + tid + 3] = acc;
        g_tab[2*REP_FLOATS + t*72 + tid + 2] = acc;
        g_tab[3*REP_FLOATS + t*72 + tid + 1] = acc;
    }
}

// ---------------------------------------------------------------------------
// Kernel 2: gather. R7 mapping (warp = 32 tokens = 536 float4s, one tile per
// warp, 2048x256 grid) with an explicit DEPTH-4 software pipeline: main table
// LDG.128s are issued 4 iterations ahead into a rotating register buffer to
// raise per-warp MLP (L1 work is fixed ~14.4us; utilization was the limiter).
// Fixup loads stay in the process stage — they hit L1 lines already fetched
// by the pipelined main loads. Streaming .cs stores (verified).
// ---------------------------------------------------------------------------
__device__ __forceinline__ void stcs128(float4* p, float4 v) {
    asm volatile("st.global.cs.v4.f32 [%0], {%1,%2,%3,%4};"
                 :: "l"(p), "f"(v.x), "f"(v.y), "f"(v.z), "f"(v.w) : "memory");
}

__global__ void __launch_bounds__(256) gather_kernel(
    const int* __restrict__ idx, float* __restrict__ out)
{
    const int lane = threadIdx.x & 31;
    const int tile = (blockIdx.x * 256 + (int)threadIdx.x) >> 5;   // 0..16383

    const int mytok = __ldg(idx + tile*32 + lane);       // token ids < 67 (8 bits)
    const int nx    = __shfl_down_sync(0xffffffffu, mytok, 1);
    const int pair  = mytok | (nx << 8);                 // {tok[lane], tok[lane+1]}
    float4* O = (float4*)out + (uint32_t)tile * 536;

    float4 buf[PD];
    int    pbuf[PD];   // pp (token|token2<<8) per in-flight iteration

    // issue stage for iteration k (compile-time k%PD indexing via unroll)
    #define GISSUE(k)                                                          \
        {                                                                      \
            const int e0 = 4*(lane + 32*(k));                                  \
            const int tk = (int)((unsigned)e0 / 67u);                          \
            const int r  = e0 - 67*tk;                                         \
            const int pp = __shfl_sync(0xffffffffu, pair, tk & 31);            \
            const int j   = tk & 3;                                            \
            const int pos = (r + 3) & ~3;                                      \
            pbuf[(k) % PD] = pp;                                               \
            buf[(k) % PD]  = __ldg((const float4*)(g_tab + j*REP_FLOATS        \
                                   + (pp & 0xff)*72 + pos));                   \
        }

    #pragma unroll
    for (int k = 0; k < PD; ++k) GISSUE(k);

    #pragma unroll
    for (int i = 0; i < 17; ++i) {
        // process iteration i
        const int e0 = 4*(lane + 32*i);
        const int tk = (int)((unsigned)e0 / 67u);
        const int r  = e0 - 67*tk;
        const int j  = tk & 3;

        float4 v = buf[i % PD];
        const int token2 = (pbuf[i % PD] >> 8) & 0xff;

        // issue iteration i+PD (uniform compile-time condition)
        if (i + PD < 17) GISSUE(i + PD);

        if (r >= 64) {                       // straddle: tail from next token (L1 hit)
            float4 w = __ldg((const float4*)(g_tab + (j+1)*REP_FLOATS + token2*72));
            if (r == 66) v.y = w.y;
            if (r >= 65) v.z = w.z;
            v.w = w.w;
        }
        if (i < 16 || lane < 24)             // quads >=536 don't exist
            stcs128(O + (lane + 32*i), v);
    }
    #undef GISSUE
}

// ---------------------------------------------------------------------------
// Launch
// ---------------------------------------------------------------------------
extern "C" void kernel_launch(void* const* d_in, const int* in_sizes, int n_in,
                              void* d_out, int out_size) {
    const int*   idx = (const int*)d_in[0];   // input_seq [64,8192] int32
    const float* emb = (const float*)d_in[1]; // embedding_table [67,50]
    const float* kap = (const float*)d_in[2]; // kappa [8,50,50]
    const float* ph  = (const float*)d_in[3]; // phi   [8,50,50]
    const float* Wo  = (const float*)d_in[4]; // W_out [50,67]
    const float* bo  = (const float*)d_in[5]; // b_out [67]
    float* out = (float*)d_out;

    table_kernel<<<VOCAB, 128>>>(emb, kap, ph, Wo, bo);
    gather_kernel<<<2048, 256>>>(idx, out);   // 16384 warps, one 32-token tile each
}